// round 4
// baseline (speedup 1.0000x reference)
#include <cuda_runtime.h>
#include <math.h>

#define MAXN 200000
#define MAXE 3200000

typedef unsigned long long u64;

// ---------------- scratch (device globals: no allocation allowed) ----------------
__device__ int   g_rowptr[MAXN + 1];
__device__ int   g_cursor[MAXN];
__device__ int   g_bsum[128];
__device__ int   g_srcp[MAXE];
__device__ __align__(16) float g_msg[(size_t)MAXE * 16];
__device__ __align__(16) float g_u[(size_t)MAXN * 24];
__device__ __align__(16) float g_z1[(size_t)MAXN * 64];
__device__ __align__(16) float g_h[(size_t)MAXN * 64];
__device__ __align__(16) float g_u2[(size_t)MAXN * 64];
__device__ __align__(16) float g_z2[(size_t)MAXN * 128];
__device__ __align__(16) float g_zeroblk[384 + 64 * 128];  // stats[384] + pooled[8192]
__device__ float g_bn1[128];
__device__ float g_bn2[256];

__device__ __forceinline__ float gelu_(float x) {
    return 0.5f * x * (1.0f + erff(x * 0.7071067811865476f));
}
__device__ __forceinline__ void red4(float* p, float a, float b, float c, float d) {
    asm volatile("red.global.add.v4.f32 [%0], {%1,%2,%3,%4};"
                 :: "l"(p), "f"(a), "f"(b), "f"(c), "f"(d) : "memory");
}
__device__ __forceinline__ u64 pk2(float x, float y) {
    u64 r; asm("mov.b64 %0,{%1,%2};" : "=l"(r) : "f"(x), "f"(y)); return r;
}
__device__ __forceinline__ void fma2(u64& d, u64 a, u64 b) {
    asm("fma.rn.f32x2 %0,%1,%2,%0;" : "+l"(d) : "l"(a), "l"(b));
}
__device__ __forceinline__ float2 up2(u64 v) {
    float2 r; asm("mov.b64 {%0,%1},%2;" : "=f"(r.x), "=f"(r.y) : "l"(v)); return r;
}

// ---------------- CSR build ----------------
__global__ void __launch_bounds__(256) k_hist(const int* __restrict__ ei,
                                              int* __restrict__ deg, int E)
{
    int e = blockIdx.x * 256 + threadIdx.x;
    if (e < E) atomicAdd(&deg[ei[E + e]], 1);
}

__global__ void __launch_bounds__(256) k_scan_part(int* __restrict__ rowptr,
                                                   int* __restrict__ bsum, int N)
{
    __shared__ int sh[256];
    int t = threadIdx.x;
    int base = blockIdx.x * 2048 + t * 8;
    int loc[8]; int s = 0;
#pragma unroll
    for (int j = 0; j < 8; j++) { int i = base + j; loc[j] = (i < N) ? rowptr[i] : 0; s += loc[j]; }
    sh[t] = s; __syncthreads();
    for (int off = 1; off < 256; off <<= 1) {
        int v = (t >= off) ? sh[t - off] : 0;
        __syncthreads();
        sh[t] += v;
        __syncthreads();
    }
    int excl = sh[t] - s;
    if (t == 255) bsum[blockIdx.x] = sh[255];
#pragma unroll
    for (int j = 0; j < 8; j++) {
        int i = base + j;
        if (i < N) { int v = loc[j]; rowptr[i] = excl; excl += v; }
    }
}

// fold top-level scan in: all threads of a block share bsum index blockIdx>>3
__global__ void __launch_bounds__(256) k_scan_add(int* __restrict__ rowptr,
                                                  int* __restrict__ cursor,
                                                  const int* __restrict__ bsum,
                                                  int N, int E)
{
    __shared__ int sbase;
    if (threadIdx.x == 0) {
        int nb = blockIdx.x >> 3;
        int s = 0;
        for (int i = 0; i < nb; i++) s += bsum[i];
        sbase = s;
    }
    __syncthreads();
    int i = blockIdx.x * 256 + threadIdx.x;
    if (i < N) {
        int v = rowptr[i] + sbase;
        rowptr[i] = v; cursor[i] = v;
    }
    if (i == 0) rowptr[N] = E;
}

// ---------------- edge MLP -> permuted msg (grouped by dst) ----------------
__global__ void __launch_bounds__(256) k_edge1(
    const int* __restrict__ ei, const float* __restrict__ ef,
    const float* __restrict__ We1, const float* __restrict__ be1,
    const float* __restrict__ We2, const float* __restrict__ be2,
    int* __restrict__ cursor, float* __restrict__ msg, int* __restrict__ srcp, int E)
{
    __shared__ float sWe1[48], sbe1[16], sbe2[16];
    __shared__ __align__(8) float sWe2[256];
    int t = threadIdx.x;
    if (t < 48)  sWe1[t] = We1[t];
    if (t < 16)  sbe1[t] = be1[t];
    if (t < 256) sWe2[t] = We2[t];
    if (t >= 48 && t < 64) sbe2[t - 48] = be2[t - 48];
    __syncthreads();

    int e = blockIdx.x * 256 + t;
    if (e >= E) return;

    float f0 = ef[3 * e], f1 = ef[3 * e + 1], f2 = ef[3 * e + 2];
    float emb[16];
#pragma unroll
    for (int j = 0; j < 16; j++) {
        float v = sbe1[j] + f0 * sWe1[j] + f1 * sWe1[16 + j] + f2 * sWe1[32 + j];
        emb[j] = gelu_(v);
    }
    u64 acc[8];
#pragma unroll
    for (int i = 0; i < 8; i++) acc[i] = pk2(sbe2[2 * i], sbe2[2 * i + 1]);
#pragma unroll
    for (int k = 0; k < 16; k++) {
        u64 ek = pk2(emb[k], emb[k]);
        const u64* wp = (const u64*)(sWe2 + k * 16);
#pragma unroll
        for (int i = 0; i < 8; i++) fma2(acc[i], ek, wp[i]);
    }
    int src = ei[e], dst = ei[E + e];
    int pos = atomicAdd(&cursor[dst], 1);
    float4* mp = (float4*)(msg + (size_t)pos * 16);
#pragma unroll
    for (int i4 = 0; i4 < 4; i4++) {
        float2 a = up2(acc[2 * i4]), b = up2(acc[2 * i4 + 1]);
        mp[i4] = make_float4(a.x, a.y, b.x, b.y);
    }
    srcp[pos] = src;
}

// ---------------- agg1 + ego -> u[N][24] (21 used) ----------------
__global__ void __launch_bounds__(256) k_agg1u(
    const int* __restrict__ rowptr, const int* __restrict__ srcp,
    const float* __restrict__ msg, const float* __restrict__ nodes,
    const float* __restrict__ Wego, const float* __restrict__ eps1,
    float* __restrict__ u, int N)
{
    __shared__ float sWe[105];
    int tid = threadIdx.x;
    if (tid < 105) sWe[tid] = Wego[tid];
    __syncthreads();

    int wid = blockIdx.x * 8 + (tid >> 5);
    if (wid >= N) return;
    int c = tid & 31;
    int beg = rowptr[wid], end = rowptr[wid + 1];
    float s = 0.f;
    if (c < 21) {
#pragma unroll 4
        for (int e = beg; e < end; e++) {
            float v;
            if (c < 5) v = __ldg(nodes + (size_t)srcp[e] * 5 + c);
            else       v = msg[(size_t)e * 16 + (c - 5)];
            s += v;
        }
        const float* nr = nodes + (size_t)wid * 5;
        float x0 = nr[0], x1 = nr[1], x2 = nr[2], x3 = nr[3], x4 = nr[4];
        float ego = x0 * sWe[c] + x1 * sWe[21 + c] + x2 * sWe[42 + c]
                  + x3 * sWe[63 + c] + x4 * sWe[84 + c];
        u[(size_t)wid * 24 + c] = fmaf(1.f + eps1[0], ego, s);
    }
}

// ---------------- agg2 + (1+eps2)h -> u2[N][64]  (2 edges/iter, float4 lanes) ----------------
__global__ void __launch_bounds__(256) k_agg2h2(
    const int* __restrict__ rowptr, const int* __restrict__ srcp,
    const float* __restrict__ h, const float* __restrict__ eps2,
    float* __restrict__ u2, int N)
{
    int wid = blockIdx.x * 8 + (threadIdx.x >> 5);
    if (wid >= N) return;
    int l = threadIdx.x & 31;
    int g = l >> 4, c4 = l & 15;
    int beg = rowptr[wid], end = rowptr[wid + 1];
    float4 a = make_float4(0.f, 0.f, 0.f, 0.f);
    int e = beg;
    for (; e + 1 < end; e += 2) {
        int s = srcp[e + g];
        float4 v = __ldg((const float4*)(h + (size_t)s * 64) + c4);
        a.x += v.x; a.y += v.y; a.z += v.z; a.w += v.w;
    }
    if (e < end && g == 0) {
        int s = srcp[e];
        float4 v = __ldg((const float4*)(h + (size_t)s * 64) + c4);
        a.x += v.x; a.y += v.y; a.z += v.z; a.w += v.w;
    }
    a.x += __shfl_down_sync(0xffffffffu, a.x, 16);
    a.y += __shfl_down_sync(0xffffffffu, a.y, 16);
    a.z += __shfl_down_sync(0xffffffffu, a.z, 16);
    a.w += __shfl_down_sync(0xffffffffu, a.w, 16);
    if (g == 0) {
        float e2 = 1.f + eps2[0];
        float4 hv = ((const float4*)(h + (size_t)wid * 64))[c4];
        float4 r = make_float4(fmaf(e2, hv.x, a.x), fmaf(e2, hv.y, a.y),
                               fmaf(e2, hv.z, a.z), fmaf(e2, hv.w, a.w));
        ((float4*)(u2 + (size_t)wid * 64))[c4] = r;
    }
}

__global__ void k_bnfin(const float* __restrict__ sums, const float* __restrict__ gamma,
                        const float* __restrict__ beta, float invN, int C,
                        float* __restrict__ bn)
{
    int c = threadIdx.x;
    if (c >= C) return;
    float mu  = sums[c] * invN;
    float var = sums[C + c] * invN - mu * mu;
    float sc  = gamma[c] * rsqrtf(var + 1e-5f);
    bn[c] = sc;
    bn[C + c] = beta[c] - mu * sc;
}

// ---------------- tiled GEMM: 128 nodes/block, thread = 2 nodes x 16 ch ----------------
// MIN: 0 plain X, 1 gelu(bn(X)).  MOUT: 0 store Z, 1 pooled reduction (C==128).
// STAT: 1 -> accumulate per-channel sum/sumsq of outputs into stats.
template<int K, int KP, int C, int MIN, int MOUT, int STAT>
__global__ void __launch_bounds__((C / 16) * 64)
k_gemm(const float* __restrict__ X, const float* __restrict__ W,
       const float* __restrict__ bias, const float* __restrict__ bn,
       float* __restrict__ Z, const int* __restrict__ batch,
       float* __restrict__ pooled, float* __restrict__ stats, int N)
{
    extern __shared__ __align__(16) float sm[];
    float* sx = sm;                 // KP * 132
    float* sw = sm + KP * 132;      // K * C
    float* sb = sw + K * C;         // C
    const int T = (C / 16) * 64;
    int tid = threadIdx.x;
    int n0 = blockIdx.x * 128;

    for (int i = tid; i < K * C / 4; i += T)
        ((float4*)sw)[i] = ((const float4*)W)[i];
    if (tid < C) sb[tid] = bias[tid];

    for (int idx = tid; idx < 128 * (KP / 4); idx += T) {
        int n = idx & 127, j = idx >> 7;
        float4 v = make_float4(0.f, 0.f, 0.f, 0.f);
        if (n0 + n < N) v = ((const float4*)(X + (size_t)(n0 + n) * KP))[j];
        if (MIN == 1) {
            int k = 4 * j;
            v.x = gelu_(fmaf(v.x, bn[k + 0], bn[K + k + 0]));
            v.y = gelu_(fmaf(v.y, bn[k + 1], bn[K + k + 1]));
            v.z = gelu_(fmaf(v.z, bn[k + 2], bn[K + k + 2]));
            v.w = gelu_(fmaf(v.w, bn[k + 3], bn[K + k + 3]));
        }
        sx[(4 * j + 0) * 132 + n] = v.x;
        sx[(4 * j + 1) * 132 + n] = v.y;
        sx[(4 * j + 2) * 132 + n] = v.z;
        sx[(4 * j + 3) * 132 + n] = v.w;
    }
    __syncthreads();

    int q = tid & 63;        // node pair index: nodes 2q, 2q+1
    int w = tid >> 6;        // channel group: 16 channels
    u64 acc[16];
#pragma unroll
    for (int i = 0; i < 16; i++) acc[i] = 0ull;

    const float* xbase = sx + 2 * q;
    const float* wbase = sw + 16 * w;
#pragma unroll 4
    for (int k = 0; k < K; k++) {
        float2 xv = *(const float2*)(xbase + k * 132);
        const u64* wp = (const u64*)(wbase + k * C);
        u64 wv[8];
#pragma unroll
        for (int i = 0; i < 8; i++) wv[i] = wp[i];
        u64 x0 = pk2(xv.x, xv.x), x1 = pk2(xv.y, xv.y);
#pragma unroll
        for (int i = 0; i < 8; i++) fma2(acc[i], x0, wv[i]);
#pragma unroll
        for (int i = 0; i < 8; i++) fma2(acc[8 + i], x1, wv[i]);
    }

    float bb[16];
#pragma unroll
    for (int i = 0; i < 16; i++) bb[i] = sb[16 * w + i];

    if (MOUT == 0) {
        float ssum[16], ssq[16];
        if (STAT) {
#pragma unroll
            for (int i = 0; i < 16; i++) { ssum[i] = 0.f; ssq[i] = 0.f; }
        }
#pragma unroll
        for (int nn = 0; nn < 2; nn++) {
            int n = n0 + 2 * q + nn;
            if (n < N) {
                float vals[16];
#pragma unroll
                for (int i = 0; i < 8; i++) {
                    float2 p = up2(acc[nn * 8 + i]);
                    vals[2 * i]     = p.x + bb[2 * i];
                    vals[2 * i + 1] = p.y + bb[2 * i + 1];
                }
                float4* zp = (float4*)(Z + (size_t)n * C + 16 * w);
#pragma unroll
                for (int i4 = 0; i4 < 4; i4++)
                    zp[i4] = make_float4(vals[4 * i4], vals[4 * i4 + 1],
                                         vals[4 * i4 + 2], vals[4 * i4 + 3]);
                if (STAT) {
#pragma unroll
                    for (int i = 0; i < 16; i++) {
                        ssum[i] += vals[i];
                        ssq[i]  += vals[i] * vals[i];
                    }
                }
            }
        }
        if (STAT) {
#pragma unroll
            for (int i = 0; i < 16; i++) {
#pragma unroll
                for (int off = 16; off >= 1; off >>= 1) {
                    ssum[i] += __shfl_xor_sync(0xffffffffu, ssum[i], off);
                    ssq[i]  += __shfl_xor_sync(0xffffffffu, ssq[i], off);
                }
            }
            if ((tid & 31) == 0) {
#pragma unroll
                for (int i = 0; i < 16; i++) {
                    atomicAdd(&stats[16 * w + i], ssum[i]);
                    atomicAdd(&stats[C + 16 * w + i], ssq[i]);
                }
            }
        }
    } else {
        float run[16];
        int curb = -1;
#pragma unroll
        for (int nn = 0; nn < 2; nn++) {
            int n = n0 + 2 * q + nn;
            if (n < N) {
                int b = batch[n];
                float vals[16];
#pragma unroll
                for (int i = 0; i < 8; i++) {
                    float2 p = up2(acc[nn * 8 + i]);
                    vals[2 * i]     = p.x + bb[2 * i];
                    vals[2 * i + 1] = p.y + bb[2 * i + 1];
                }
                if (b != curb) {
                    if (curb >= 0) {
                        float* pp = pooled + (size_t)curb * 128 + 16 * w;
                        red4(pp,      run[0],  run[1],  run[2],  run[3]);
                        red4(pp + 4,  run[4],  run[5],  run[6],  run[7]);
                        red4(pp + 8,  run[8],  run[9],  run[10], run[11]);
                        red4(pp + 12, run[12], run[13], run[14], run[15]);
                    }
                    curb = b;
#pragma unroll
                    for (int i = 0; i < 16; i++) run[i] = vals[i];
                } else {
#pragma unroll
                    for (int i = 0; i < 16; i++) run[i] += vals[i];
                }
            }
        }
        if (curb >= 0) {
            float* pp = pooled + (size_t)curb * 128 + 16 * w;
            red4(pp,      run[0],  run[1],  run[2],  run[3]);
            red4(pp + 4,  run[4],  run[5],  run[6],  run[7]);
            red4(pp + 8,  run[8],  run[9],  run[10], run[11]);
            red4(pp + 12, run[12], run[13], run[14], run[15]);
        }
    }
}

// ---------------- out = gelu(pooled @ Wp + bp) ----------------
__global__ void __launch_bounds__(128) k_out(
    const float* __restrict__ pooled, const float* __restrict__ Wp,
    const float* __restrict__ bp, float* __restrict__ out, int B)
{
    int b = blockIdx.x, c = threadIdx.x;
    const float* pr = pooled + (size_t)b * 128;
    float a = bp[c];
#pragma unroll 8
    for (int k = 0; k < 128; k++) a += pr[k] * Wp[k * 128 + c];
    out[(size_t)b * 128 + c] = gelu_(a);
}

// ---------------- launcher ----------------
extern "C" void kernel_launch(void* const* d_in, const int* in_sizes, int n_in,
                              void* d_out, int out_size)
{
    const float* nodes = (const float*)d_in[0];
    const int*   ei    = (const int*)d_in[1];
    const float* ef    = (const float*)d_in[2];
    const int*   batch = (const int*)d_in[3];
    const float* We1  = (const float*)d_in[5];
    const float* be1  = (const float*)d_in[6];
    const float* We2  = (const float*)d_in[7];
    const float* be2  = (const float*)d_in[8];
    const float* Wego = (const float*)d_in[9];
    const float* W1a  = (const float*)d_in[10];
    const float* b1a  = (const float*)d_in[11];
    const float* g1   = (const float*)d_in[12];
    const float* bta1 = (const float*)d_in[13];
    const float* W1b  = (const float*)d_in[14];
    const float* b1b  = (const float*)d_in[15];
    const float* eps1 = (const float*)d_in[16];
    const float* W2a  = (const float*)d_in[17];
    const float* b2a  = (const float*)d_in[18];
    const float* g2   = (const float*)d_in[19];
    const float* bta2 = (const float*)d_in[20];
    const float* W2b  = (const float*)d_in[21];
    const float* b2b  = (const float*)d_in[22];
    const float* eps2 = (const float*)d_in[23];
    const float* Wp   = (const float*)d_in[24];
    const float* bp   = (const float*)d_in[25];

    int N = in_sizes[0] / 5;
    int E = in_sizes[1] / 2;
    int B = out_size / 128;

    int *rowptr, *cursor, *bsum, *srcp;
    float *msg, *u, *z1, *h, *u2, *z2, *zeroblk, *bn1, *bn2;
    cudaGetSymbolAddress((void**)&rowptr,  g_rowptr);
    cudaGetSymbolAddress((void**)&cursor,  g_cursor);
    cudaGetSymbolAddress((void**)&bsum,    g_bsum);
    cudaGetSymbolAddress((void**)&srcp,    g_srcp);
    cudaGetSymbolAddress((void**)&msg,     g_msg);
    cudaGetSymbolAddress((void**)&u,       g_u);
    cudaGetSymbolAddress((void**)&z1,      g_z1);
    cudaGetSymbolAddress((void**)&h,       g_h);
    cudaGetSymbolAddress((void**)&u2,      g_u2);
    cudaGetSymbolAddress((void**)&z2,      g_z2);
    cudaGetSymbolAddress((void**)&zeroblk, g_zeroblk);
    cudaGetSymbolAddress((void**)&bn1,     g_bn1);
    cudaGetSymbolAddress((void**)&bn2,     g_bn2);
    float* stats  = zeroblk;
    float* pooled = zeroblk + 384;

    cudaMemsetAsync(rowptr,  0, (size_t)(N + 1) * sizeof(int), 0);
    cudaMemsetAsync(zeroblk, 0, (384 + (size_t)B * 128) * sizeof(float), 0);

    float invN = 1.0f / (float)N;
    int nScanBlocks = (N + 2047) / 2048;

    // CSR build
    k_hist<<<(E + 255) / 256, 256>>>(ei, rowptr, E);
    k_scan_part<<<nScanBlocks, 256>>>(rowptr, bsum, N);
    k_scan_add<<<(N + 255) / 256, 256>>>(rowptr, cursor, bsum, N, E);

    // layer 1
    k_edge1<<<(E + 255) / 256, 256>>>(ei, ef, We1, be1, We2, be2, cursor, msg, srcp, E);
    k_agg1u<<<(N + 7) / 8, 256>>>(rowptr, srcp, msg, nodes, Wego, eps1, u, N);

    const int SM1 = (24 * 132 + 21 * 64 + 64) * 4;
    const int SMH = (64 * 132 + 64 * 64 + 64) * 4;
    const int SM2 = (64 * 132 + 64 * 128 + 128) * 4;
    const int SM3 = (128 * 132 + 128 * 128 + 128) * 4;
    int nTiles = (N + 127) / 128;

    k_gemm<21, 24, 64, 0, 0, 1><<<nTiles, 256, SM1>>>(u, W1a, b1a, nullptr, z1,
                                                      nullptr, nullptr, stats, N);
    k_bnfin<<<1, 64>>>(stats, g1, bta1, invN, 64, bn1);

    cudaFuncSetAttribute((const void*)k_gemm<64, 64, 64, 1, 0, 0>,
                         cudaFuncAttributeMaxDynamicSharedMemorySize, SMH);
    k_gemm<64, 64, 64, 1, 0, 0><<<nTiles, 256, SMH>>>(z1, W1b, b1b, bn1, h,
                                                      nullptr, nullptr, nullptr, N);

    // layer 2
    k_agg2h2<<<(N + 7) / 8, 256>>>(rowptr, srcp, h, eps2, u2, N);

    cudaFuncSetAttribute((const void*)k_gemm<64, 64, 128, 0, 0, 1>,
                         cudaFuncAttributeMaxDynamicSharedMemorySize, SM2);
    k_gemm<64, 64, 128, 0, 0, 1><<<nTiles, 512, SM2>>>(u2, W2a, b2a, nullptr, z2,
                                                       nullptr, nullptr, stats + 128, N);
    k_bnfin<<<1, 128>>>(stats + 128, g2, bta2, invN, 128, bn2);

    cudaFuncSetAttribute((const void*)k_gemm<128, 128, 128, 1, 1, 0>,
                         cudaFuncAttributeMaxDynamicSharedMemorySize, SM3);
    k_gemm<128, 128, 128, 1, 1, 0><<<nTiles, 512, SM3>>>(z2, W2b, b2b, bn2, nullptr,
                                                         batch, pooled, nullptr, N);

    k_out<<<B, 128>>>(pooled, Wp, bp, (float*)d_out, B);
}